// round 1
// baseline (speedup 1.0000x reference)
#include <cuda_runtime.h>
#include <math.h>

#define TT 8192
#define KK 1024
#define DD 1024
#define NTH 1024
#define MAXGRID 256
#define START_TAG 1022
#define STOP_TAG 1023
#define NEGV (-10000.0f)
#define LOG2E 1.4426950408889634f
#define LN2F 0.6931471805599453f

// ---------------- device scratch (no allocs allowed) ----------------
__device__ float g_ta2[KK * KK];          // ta * log2(e)
__device__ float g_df2[KK * KK];          // (ti - ta) * log2(e)
__device__ float g_fv[2][KK];             // double-buffered forward variables (log2 domain)
__device__ float g_gmaxb[2][MAXGRID];     // per-CTA local maxima of fv
__device__ float g_gate[TT + 1];          // gates per step + terminal gate
__device__ float g_uc[TT], g_vc[TT], g_uu[TT], g_vu[TT];
__device__ unsigned g_bar;                // monotonic grid-barrier counter

__device__ __forceinline__ float ex2f(float x) {
    float y; asm("ex2.approx.f32 %0, %1;" : "=f"(y) : "f"(x)); return y;
}
__device__ __forceinline__ float lg2f(float x) {
    float y; asm("lg2.approx.f32 %0, %1;" : "=f"(y) : "f"(x)); return y;
}
__device__ __forceinline__ unsigned ld_acq(const unsigned* p) {
    unsigned v;
    asm volatile("ld.acquire.gpu.u32 %0, [%1];" : "=r"(v) : "l"(p) : "memory");
    return v;
}

// ---------------- prep: scale transition matrices ----------------
__global__ void prep_trans(const float* __restrict__ ti, const float* __restrict__ ta) {
    int i = blockIdx.x * blockDim.x + threadIdx.x;
    if (i < KK * KK) {
        float a = ta[i], b = ti[i];
        g_ta2[i] = a * LOG2E;
        g_df2[i] = (b - a) * LOG2E;
    }
}

// ---------------- prep: per-row dot products with gate weight halves ----------------
// u = reps[t] . w[0:D]  (applied to the "prev" slot), v = reps[t] . w[D:2D] (the "cur" slot)
__global__ void prep_dots(const float* __restrict__ reps,
                          const float* __restrict__ wc,
                          const float* __restrict__ wu) {
    int t = blockIdx.x, tid = threadIdx.x;                 // 256 threads
    const float4 a  = ((const float4*)(reps + (size_t)t * DD))[tid];
    const float4 c0 = ((const float4*)wc)[tid];
    const float4 c1 = ((const float4*)wc)[tid + 256];
    const float4 u0 = ((const float4*)wu)[tid];
    const float4 u1 = ((const float4*)wu)[tid + 256];
    float v0 = a.x * c0.x + a.y * c0.y + a.z * c0.z + a.w * c0.w;
    float v1 = a.x * c1.x + a.y * c1.y + a.z * c1.z + a.w * c1.w;
    float v2 = a.x * u0.x + a.y * u0.y + a.z * u0.z + a.w * u0.w;
    float v3 = a.x * u1.x + a.y * u1.y + a.z * u1.z + a.w * u1.w;
    #pragma unroll
    for (int o = 16; o; o >>= 1) {
        v0 += __shfl_xor_sync(0xffffffffu, v0, o);
        v1 += __shfl_xor_sync(0xffffffffu, v1, o);
        v2 += __shfl_xor_sync(0xffffffffu, v2, o);
        v3 += __shfl_xor_sync(0xffffffffu, v3, o);
    }
    __shared__ float sm[8][4];
    int lane = tid & 31, w = tid >> 5;
    if (lane == 0) { sm[w][0] = v0; sm[w][1] = v1; sm[w][2] = v2; sm[w][3] = v3; }
    __syncthreads();
    if (tid == 0) {
        float t0 = 0, t1 = 0, t2 = 0, t3 = 0;
        for (int i = 0; i < 8; i++) { t0 += sm[i][0]; t1 += sm[i][1]; t2 += sm[i][2]; t3 += sm[i][3]; }
        g_uc[t] = t0; g_vc[t] = t1; g_uu[t] = t2; g_vu[t] = t3;
    }
}

// ---------------- prep: gates ----------------
__global__ void prep_gate(const int* __restrict__ spk) {
    int t = blockIdx.x * blockDim.x + threadIdx.x;
    if (t < TT) {
        int pt = (t > 0) ? t - 1 : 0;
        bool use_change = (t > 0) && (spk[t] != 0);
        float x = use_change ? (g_uc[pt] + g_vc[t]) : (g_uu[pt] + g_vu[t]);
        g_gate[t] = 1.0f / (1.0f + expf(-x));
    } else if (t == TT) {
        float x = g_uu[TT - 1] + g_vu[TT - 1];
        g_gate[TT] = 1.0f / (1.0f + expf(-x));
    }
}

// ---------------- init ----------------
__global__ void init_k() {
    int tid = threadIdx.x;   // 1024 threads
    g_fv[0][tid] = (tid == START_TAG) ? 0.0f : NEGV * LOG2E;
    if (tid < MAXGRID) { g_gmaxb[0][tid] = 0.0f; g_gmaxb[1][tid] = 0.0f; }
    if (tid == 0) g_bar = 0u;
}

// ---------------- persistent CRF forward ----------------
__global__ void __launch_bounds__(NTH, 1)
crf_main(const float* __restrict__ feats, float* __restrict__ out) {
    const int G   = gridDim.x;
    const int g   = blockIdx.x;
    const int tid = threadIdx.x;
    const int lane = tid & 31;
    const int wid  = tid >> 5;
    const int lrow = tid >> 7;            // 0..7 : row index within CTA
    const int j0   = (tid & 127) << 3;    // 8 prev-tags per thread
    const int r0 = (g * KK) / G;
    const int r1 = ((g + 1) * KK) / G;
    const int R  = r1 - r0;               // 6 or 7 rows per CTA (G=148)
    const bool active = lrow < R;
    const int row = r0 + lrow;

    // pin this thread's matrix slice in registers (loaded once, reused 8192 steps)
    float ta2r[8], df2r[8];
    if (active) {
        const float4* pa = (const float4*)(g_ta2 + (size_t)row * KK + j0);
        const float4* pd = (const float4*)(g_df2 + (size_t)row * KK + j0);
        float4 a0 = pa[0], a1 = pa[1], d0 = pd[0], d1 = pd[1];
        ta2r[0]=a0.x; ta2r[1]=a0.y; ta2r[2]=a0.z; ta2r[3]=a0.w;
        ta2r[4]=a1.x; ta2r[5]=a1.y; ta2r[6]=a1.z; ta2r[7]=a1.w;
        df2r[0]=d0.x; df2r[1]=d0.y; df2r[2]=d0.z; df2r[3]=d0.w;
        df2r[4]=d1.x; df2r[5]=d1.y; df2r[6]=d1.z; df2r[7]=d1.w;
    } else {
        #pragma unroll
        for (int q = 0; q < 8; q++) { ta2r[q] = 0.0f; df2r[q] = 0.0f; }
    }

    __shared__ __align__(16) float s_fvp[KK];
    __shared__ float s_part[8][4];
    __shared__ float s_new[8];
    __shared__ float s_feat[8];
    __shared__ float s_gmax;
    __shared__ float s_red[32];

    unsigned target = 0;
    for (int t = 0; t < TT; ++t) {
        const int p = t & 1;

        // prefetch this step's emission scores (DRAM latency hidden behind compute)
        if (wid == 1 && lane < R)
            s_feat[lane] = feats[(size_t)t * KK + r0 + lane] * LOG2E;

        const float gate = g_gate[t];
        float fvv = __ldcg(&g_fv[p][tid]);          // .cg: bypass (incoherent) L1

        if (wid == 0) {                              // global max of fv from per-CTA maxima
            float m = -3.4e38f;
            for (int i = lane; i < G; i += 32) m = fmaxf(m, __ldcg(&g_gmaxb[p][i]));
            #pragma unroll
            for (int o = 16; o; o >>= 1) m = fmaxf(m, __shfl_xor_sync(0xffffffffu, m, o));
            if (lane == 0) s_gmax = m;
        }
        __syncthreads();
        const float gm = s_gmax;
        s_fvp[tid] = fvv - gm;
        __syncthreads();

        // inner compute: 8 EX2 per thread (MUFU-bound segment)
        float acc = 0.0f;
        if (active) {
            float4 f0 = *(const float4*)&s_fvp[j0];
            float4 f1 = *(const float4*)&s_fvp[j0 + 4];
            float a = 0.0f, b = 0.0f;
            a += ex2f(f0.x + fmaf(gate, df2r[0], ta2r[0]));
            b += ex2f(f0.y + fmaf(gate, df2r[1], ta2r[1]));
            a += ex2f(f0.z + fmaf(gate, df2r[2], ta2r[2]));
            b += ex2f(f0.w + fmaf(gate, df2r[3], ta2r[3]));
            a += ex2f(f1.x + fmaf(gate, df2r[4], ta2r[4]));
            b += ex2f(f1.y + fmaf(gate, df2r[5], ta2r[5]));
            a += ex2f(f1.z + fmaf(gate, df2r[6], ta2r[6]));
            b += ex2f(f1.w + fmaf(gate, df2r[7], ta2r[7]));
            acc = a + b;
        }
        // warp = 32 threads of one row -> warp sum
        #pragma unroll
        for (int o = 16; o; o >>= 1) acc += __shfl_xor_sync(0xffffffffu, acc, o);
        if (lane == 0) s_part[lrow][wid & 3] = acc;
        __syncthreads();

        // warp 0 finalizes all rows: combine 4 warp-partials per row, log2, write fv_new
        if (wid == 0) {
            int rr = lane >> 2;
            float v = s_part[rr][lane & 3];
            v += __shfl_xor_sync(0xffffffffu, v, 1);
            v += __shfl_xor_sync(0xffffffffu, v, 2);
            if ((lane & 3) == 0 && rr < R) {
                float fvnew = gm + s_feat[rr] + lg2f(v);
                g_fv[p ^ 1][r0 + rr] = fvnew;
                s_new[rr] = fvnew;
            }
        }
        __syncthreads();

        if (tid == 0) {
            float m = s_new[0];
            for (int k2 = 1; k2 < R; k2++) m = fmaxf(m, s_new[k2]);
            g_gmaxb[p ^ 1][g] = m;
            __threadfence();                 // release fv/gmax writes
            atomicAdd(&g_bar, 1u);
        }
        target += (unsigned)G;
        if (tid == 0) {
            while (ld_acq(&g_bar) < target) { }   // grid barrier (all CTAs co-resident)
        }
        __syncthreads();
    }

    // ---------------- terminal: CTA owning STOP row ----------------
    if (g == G - 1) {
        const float gT = g_gate[TT];
        const bool mine = (lrow == R - 1);        // row == STOP_TAG
        float term[8];
        float lm = -3.4e38f;
        if (mine) {
            #pragma unroll
            for (int q = 0; q < 8; q++) {
                float fvf = __ldcg(&g_fv[0][j0 + q]);   // TT even -> final buffer is 0
                term[q] = fvf + fmaf(gT, df2r[q], ta2r[q]);
                lm = fmaxf(lm, term[q]);
            }
        }
        #pragma unroll
        for (int o = 16; o; o >>= 1) lm = fmaxf(lm, __shfl_xor_sync(0xffffffffu, lm, o));
        if (lane == 0) s_red[wid] = lm;
        __syncthreads();
        if (wid == 0) {
            float m = s_red[lane];
            #pragma unroll
            for (int o = 16; o; o >>= 1) m = fmaxf(m, __shfl_xor_sync(0xffffffffu, m, o));
            if (lane == 0) s_gmax = m;
        }
        __syncthreads();
        const float M = s_gmax;
        float s = 0.0f;
        if (mine) {
            #pragma unroll
            for (int q = 0; q < 8; q++) s += ex2f(term[q] - M);
        }
        #pragma unroll
        for (int o = 16; o; o >>= 1) s += __shfl_xor_sync(0xffffffffu, s, o);
        if (lane == 0) s_red[wid] = s;
        __syncthreads();
        if (tid == 0) {
            float tot = 0.0f;
            for (int w = 0; w < 32; w++) tot += s_red[w];
            out[0] = (M + lg2f(tot)) * LN2F;     // back to natural log
        }
    }
}

// ---------------- launch ----------------
extern "C" void kernel_launch(void* const* d_in, const int* in_sizes, int n_in,
                              void* d_out, int out_size) {
    const float* feats = (const float*)d_in[0];
    const float* reps  = (const float*)d_in[1];
    const float* wc    = (const float*)d_in[2];
    const float* wu    = (const float*)d_in[3];
    const float* ti    = (const float*)d_in[4];
    const float* ta    = (const float*)d_in[5];
    const int*   spk   = (const int*)d_in[6];

    int dev = 0; cudaGetDevice(&dev);
    int sm = 148;
    cudaDeviceGetAttribute(&sm, cudaDevAttrMultiProcessorCount, dev);
    int grid = sm;
    if (grid > MAXGRID) grid = MAXGRID;
    if (grid < 128) grid = 128;    // row mapping needs <=8 rows/CTA; B200 has 148 SMs

    prep_trans<<<(KK * KK + 255) / 256, 256>>>(ti, ta);
    prep_dots<<<TT, 256>>>(reps, wc, wu);
    prep_gate<<<(TT + 1 + 255) / 256, 256>>>(spk);
    init_k<<<1, 1024>>>();
    crf_main<<<grid, NTH>>>(feats, (float*)d_out);
}

// round 4
// speedup vs baseline: 1.1164x; 1.1164x over previous
#include <cuda_runtime.h>
#include <math.h>

#define TT 8192
#define KK 1024
#define DD 1024
#define NTH 1024
#define START_TAG 1022
#define STOP_TAG 1023
#define NEGV (-10000.0f)
#define LOG2E 1.4426950408889634f
#define LN2F 0.6931471805599453f

// ---------------- device scratch (no allocs allowed) ----------------
__device__ float g_ta2[KK * KK];                  // ta * log2(e)
__device__ float g_df2[KK * KK];                  // (ti - ta) * log2(e)
__device__ unsigned long long g_fvE[2][KK];       // (epoch<<32) | fv_bits, double-buffered
__device__ float g_gate[TT + 1];
__device__ float g_uc[TT], g_vc[TT], g_uu[TT], g_vu[TT];

__device__ __forceinline__ float ex2f(float x) {
    float y; asm("ex2.approx.f32 %0, %1;" : "=f"(y) : "f"(x)); return y;
}
__device__ __forceinline__ float lg2f(float x) {
    float y; asm("lg2.approx.f32 %0, %1;" : "=f"(y) : "f"(x)); return y;
}
// inf-proof helpers: clamp exp2 arg; floor log2 input
__device__ __forceinline__ float ex2s(float x) { return ex2f(fminf(x, 126.0f)); }
__device__ __forceinline__ float lg2s(float v) { return lg2f(fmaxf(v, 1e-37f)); }

__device__ __forceinline__ unsigned long long ldcg_u64(const unsigned long long* p) {
    unsigned long long v;
    asm volatile("ld.global.cg.u64 %0, [%1];" : "=l"(v) : "l"(p) : "memory");
    return v;
}
__device__ __forceinline__ void stcg_u64(unsigned long long* p, unsigned long long v) {
    asm volatile("st.global.cg.u64 [%0], %1;" :: "l"(p), "l"(v) : "memory");
}

// ---------------- prep: scale transition matrices ----------------
__global__ void prep_trans(const float* __restrict__ ti, const float* __restrict__ ta) {
    int i = blockIdx.x * blockDim.x + threadIdx.x;
    if (i < KK * KK) {
        float a = ta[i], b = ti[i];
        g_ta2[i] = a * LOG2E;
        g_df2[i] = (b - a) * LOG2E;
    }
}

// ---------------- prep: per-row dots with gate weight halves ----------------
__global__ void prep_dots(const float* __restrict__ reps,
                          const float* __restrict__ wc,
                          const float* __restrict__ wu) {
    int t = blockIdx.x, tid = threadIdx.x;                 // 256 threads
    const float4 a  = ((const float4*)(reps + (size_t)t * DD))[tid];
    const float4 c0 = ((const float4*)wc)[tid];
    const float4 c1 = ((const float4*)wc)[tid + 256];
    const float4 u0 = ((const float4*)wu)[tid];
    const float4 u1 = ((const float4*)wu)[tid + 256];
    float v0 = a.x * c0.x + a.y * c0.y + a.z * c0.z + a.w * c0.w;
    float v1 = a.x * c1.x + a.y * c1.y + a.z * c1.z + a.w * c1.w;
    float v2 = a.x * u0.x + a.y * u0.y + a.z * u0.z + a.w * u0.w;
    float v3 = a.x * u1.x + a.y * u1.y + a.z * u1.z + a.w * u1.w;
    #pragma unroll
    for (int o = 16; o; o >>= 1) {
        v0 += __shfl_xor_sync(0xffffffffu, v0, o);
        v1 += __shfl_xor_sync(0xffffffffu, v1, o);
        v2 += __shfl_xor_sync(0xffffffffu, v2, o);
        v3 += __shfl_xor_sync(0xffffffffu, v3, o);
    }
    __shared__ float sm[8][4];
    int lane = tid & 31, w = tid >> 5;
    if (lane == 0) { sm[w][0] = v0; sm[w][1] = v1; sm[w][2] = v2; sm[w][3] = v3; }
    __syncthreads();
    if (tid == 0) {
        float t0 = 0, t1 = 0, t2 = 0, t3 = 0;
        for (int i = 0; i < 8; i++) { t0 += sm[i][0]; t1 += sm[i][1]; t2 += sm[i][2]; t3 += sm[i][3]; }
        g_uc[t] = t0; g_vc[t] = t1; g_uu[t] = t2; g_vu[t] = t3;
    }
}

// ---------------- prep: gates ----------------
__global__ void prep_gate(const int* __restrict__ spk) {
    int t = blockIdx.x * blockDim.x + threadIdx.x;
    if (t < TT) {
        int pt = (t > 0) ? t - 1 : 0;
        bool use_change = (t > 0) && (spk[t] != 0);
        float x = use_change ? (g_uc[pt] + g_vc[t]) : (g_uu[pt] + g_vu[t]);
        g_gate[t] = 1.0f / (1.0f + expf(-x));
    } else if (t == TT) {
        float x = g_uu[TT - 1] + g_vu[TT - 1];
        g_gate[TT] = 1.0f / (1.0f + expf(-x));
    }
}

// ---------------- init: epoch/value pairs ----------------
__global__ void init_k() {
    int tid = threadIdx.x;   // 1024 threads
    float v0 = (tid == START_TAG) ? 0.0f : NEGV * LOG2E;
    g_fvE[0][tid] = (unsigned long long)__float_as_uint(v0);         // epoch 0
    g_fvE[1][tid] = 0xFFFFFFFF00000000ULL;                           // sentinel epoch
}

// ---------------- persistent CRF forward (data-flow barrier) ----------------
__global__ void __launch_bounds__(NTH, 1)
crf_main(const float* __restrict__ feats, float* __restrict__ out) {
    const int G   = gridDim.x;
    const int g   = blockIdx.x;
    const int tid = threadIdx.x;
    const int lane = tid & 31;
    const int wid  = tid >> 5;
    const int lrow = tid >> 7;            // 0..7 : row index within CTA
    const int j0   = (tid & 127) << 3;    // 8 prev-tags per thread
    const int r0 = (g * KK) / G;
    const int r1 = ((g + 1) * KK) / G;
    const int R  = r1 - r0;               // rows per CTA (<= 8)
    const bool active = lrow < R;
    const int row = r0 + lrow;

    // pin matrix slice in registers (loaded once, reused 8192 steps)
    float ta2r[8], df2r[8];
    if (active) {
        const float4* pa = (const float4*)(g_ta2 + (size_t)row * KK + j0);
        const float4* pd = (const float4*)(g_df2 + (size_t)row * KK + j0);
        float4 a0 = pa[0], a1 = pa[1], d0 = pd[0], d1 = pd[1];
        ta2r[0]=a0.x; ta2r[1]=a0.y; ta2r[2]=a0.z; ta2r[3]=a0.w;
        ta2r[4]=a1.x; ta2r[5]=a1.y; ta2r[6]=a1.z; ta2r[7]=a1.w;
        df2r[0]=d0.x; df2r[1]=d0.y; df2r[2]=d0.z; df2r[3]=d0.w;
        df2r[4]=d1.x; df2r[5]=d1.y; df2r[6]=d1.z; df2r[7]=d1.w;
    } else {
        #pragma unroll
        for (int q = 0; q < 8; q++) { ta2r[q] = 0.0f; df2r[q] = 0.0f; }
    }

    __shared__ __align__(16) float s_fvp[KK];
    __shared__ float s_part[8][4];
    __shared__ float s_feat[2][8];        // parity double-buffered
    __shared__ float s_red[32];
    __shared__ float s_m;

    for (int t = 0; t < TT; ++t) {
        const int p = t & 1;

        // prefetch this step's emission scores (overlaps the poll + compute)
        if (wid == 1 && lane < R)
            s_feat[p][lane] = feats[(size_t)t * KK + r0 + lane] * LOG2E;

        const float gate = g_gate[t];

        // data-flow barrier: poll own (epoch|value) pair; 64-bit store is atomic,
        // so matching epoch implies valid value. No fences, no counters.
        unsigned long long pk;
        const unsigned ee = (unsigned)t;
        pk = ldcg_u64(&g_fvE[p][tid]);
        while ((unsigned)(pk >> 32) != ee) {
            __nanosleep(32);                       // throttle only真 stragglers
            pk = ldcg_u64(&g_fvE[p][tid]);
        }
        s_fvp[tid] = __uint_as_float((unsigned)pk);
        __syncthreads();

        // shift reference: 4-sample max of fv (ref cancels exactly in
        // fvnew = ref + feat + lg2(v); per-CTA refs need no agreement).
        float ref;
        if (t) {
            ref = fmaxf(fmaxf(s_fvp[0], s_fvp[256]), fmaxf(s_fvp[512], s_fvp[768]));
        } else {
            ref = 0.0f;
        }

        // inner compute: 8 EX2 per thread (MUFU-bound segment), clamped (no inf possible)
        float acc = 0.0f;
        if (active) {
            float4 f0 = *(const float4*)&s_fvp[j0];
            float4 f1 = *(const float4*)&s_fvp[j0 + 4];
            float a = 0.0f, b = 0.0f;
            a += ex2s((f0.x - ref) + fmaf(gate, df2r[0], ta2r[0]));
            b += ex2s((f0.y - ref) + fmaf(gate, df2r[1], ta2r[1]));
            a += ex2s((f0.z - ref) + fmaf(gate, df2r[2], ta2r[2]));
            b += ex2s((f0.w - ref) + fmaf(gate, df2r[3], ta2r[3]));
            a += ex2s((f1.x - ref) + fmaf(gate, df2r[4], ta2r[4]));
            b += ex2s((f1.y - ref) + fmaf(gate, df2r[5], ta2r[5]));
            a += ex2s((f1.z - ref) + fmaf(gate, df2r[6], ta2r[6]));
            b += ex2s((f1.w - ref) + fmaf(gate, df2r[7], ta2r[7]));
            acc = a + b;
        }
        #pragma unroll
        for (int o = 16; o; o >>= 1) acc += __shfl_xor_sync(0xffffffffu, acc, o);
        if (lane == 0) s_part[lrow][wid & 3] = acc;
        __syncthreads();

        // warp 0 finalizes all rows: combine partials, guarded log2, publish (epoch|value)
        if (wid == 0) {
            int rr = lane >> 2;
            float v = s_part[rr][lane & 3];
            v += __shfl_xor_sync(0xffffffffu, v, 1);
            v += __shfl_xor_sync(0xffffffffu, v, 2);
            if ((lane & 3) == 0 && rr < R) {
                float fvnew = ref + s_feat[p][rr] + lg2s(v);   // finite always
                unsigned long long packed =
                    ((unsigned long long)(unsigned)(t + 1) << 32) | __float_as_uint(fvnew);
                stcg_u64(&g_fvE[p ^ 1][r0 + rr], packed);
            }
        }
        // no trailing sync needed: next-iter smem writes are ordered behind the
        // staging __syncthreads, which warp 0 joins only after finalize.
    }

    // ---------------- terminal: CTA owning STOP row ----------------
    if (g == G - 1) {
        const float gT = g_gate[TT];
        const bool mine = (lrow == R - 1);          // row == STOP_TAG
        float term[8];
        float lm = -3.0e38f;
        if (mine) {
            #pragma unroll
            for (int q = 0; q < 8; q++) {
                unsigned long long pk;
                do { pk = ldcg_u64(&g_fvE[0][j0 + q]); }       // TT even -> buffer 0
                while ((unsigned)(pk >> 32) != (unsigned)TT);
                float fvf = __uint_as_float((unsigned)pk);
                term[q] = fvf + fmaf(gT, df2r[q], ta2r[q]);
                lm = fmaxf(lm, term[q]);
            }
        }
        #pragma unroll
        for (int o = 16; o; o >>= 1) lm = fmaxf(lm, __shfl_xor_sync(0xffffffffu, lm, o));
        if (lane == 0) s_red[wid] = lm;
        __syncthreads();
        if (wid == 0) {
            float m = s_red[lane];
            #pragma unroll
            for (int o = 16; o; o >>= 1) m = fmaxf(m, __shfl_xor_sync(0xffffffffu, m, o));
            if (lane == 0) s_m = m;
        }
        __syncthreads();
        const float M = s_m;
        float s = 0.0f;
        if (mine) {
            #pragma unroll
            for (int q = 0; q < 8; q++) s += ex2s(term[q] - M);
        }
        #pragma unroll
        for (int o = 16; o; o >>= 1) s += __shfl_xor_sync(0xffffffffu, s, o);
        if (lane == 0) s_red[wid] = s;
        __syncthreads();
        if (tid == 0) {
            float tot = 0.0f;
            for (int w = 0; w < 32; w++) tot += s_red[w];
            out[0] = (M + lg2s(tot)) * LN2F;        // back to natural log
        }
    }
}

// ---------------- launch ----------------
extern "C" void kernel_launch(void* const* d_in, const int* in_sizes, int n_in,
                              void* d_out, int out_size) {
    const float* feats = (const float*)d_in[0];
    const float* reps  = (const float*)d_in[1];
    const float* wc    = (const float*)d_in[2];
    const float* wu    = (const float*)d_in[3];
    const float* ti    = (const float*)d_in[4];
    const float* ta    = (const float*)d_in[5];
    const int*   spk   = (const int*)d_in[6];

    int dev = 0; cudaGetDevice(&dev);
    int sm = 148;
    cudaDeviceGetAttribute(&sm, cudaDevAttrMultiProcessorCount, dev);
    int grid = sm;
    if (grid > 256) grid = 256;
    if (grid < 128) grid = 128;    // row mapping needs <=8 rows/CTA

    prep_trans<<<(KK * KK + 255) / 256, 256>>>(ti, ta);
    prep_dots<<<TT, 256>>>(reps, wc, wu);
    prep_gate<<<(TT + 1 + 255) / 256, 256>>>(spk);
    init_k<<<1, 1024>>>();
    crf_main<<<grid, NTH>>>(feats, (float*)d_out);
}